// round 2
// baseline (speedup 1.0000x reference)
#include <cuda_runtime.h>
#include <math.h>

#define MROWS 8192   // B*T
#define KDIM  1024
#define TLEN  2048
#define NHEAD 16
#define HS    64

// Scratch (alloc-free rule: device globals)
__device__ float g_q[MROWS * KDIM];
__device__ float g_k[MROWS * KDIM];
__device__ float g_v[MROWS * KDIM];
__device__ float g_attn[MROWS * KDIM];

// ---------------------------------------------------------------------------
// C = A @ W^T (+bias). A: (M, KDIM) row-major. W: (N, KDIM) row-major.
// Tile 128x128x16, 256 threads, 8x8 per thread.
// which: 0->C=g_q, 1->C=g_k, 2->C=g_v, 3->A=g_attn, C=Cx
// ---------------------------------------------------------------------------
__global__ __launch_bounds__(256) void gemm_nt(const float* __restrict__ Ax,
                                               const float* __restrict__ W,
                                               const float* __restrict__ bias,
                                               float* __restrict__ Cx,
                                               int which)
{
    const float* A = (which == 3) ? g_attn : Ax;
    float* C = (which == 0) ? g_q : (which == 1) ? g_k : (which == 2) ? g_v : Cx;

    __shared__ __align__(16) float As[16][132];
    __shared__ __align__(16) float Bs[16][132];

    const int tid = threadIdx.x;
    const int tx = tid & 15;
    const int ty = tid >> 4;
    const int row0 = blockIdx.y * 128;
    const int col0 = blockIdx.x * 128;

    float acc[8][8];
#pragma unroll
    for (int i = 0; i < 8; i++)
#pragma unroll
        for (int j = 0; j < 8; j++) acc[i][j] = 0.f;

    for (int k0 = 0; k0 < KDIM; k0 += 16) {
        // Load 128x16 tiles of A and W, stored transposed (k-major) in smem.
#pragma unroll
        for (int it = 0; it < 2; it++) {
            int idx = it * 256 + tid;          // 0..511
            int m  = idx >> 2;                 // 0..127
            int kq = (idx & 3) << 2;           // 0,4,8,12
            float4 va = *(const float4*)(A + (size_t)(row0 + m) * KDIM + k0 + kq);
            As[kq + 0][m] = va.x; As[kq + 1][m] = va.y;
            As[kq + 2][m] = va.z; As[kq + 3][m] = va.w;
            float4 vb = *(const float4*)(W + (size_t)(col0 + m) * KDIM + k0 + kq);
            Bs[kq + 0][m] = vb.x; Bs[kq + 1][m] = vb.y;
            Bs[kq + 2][m] = vb.z; Bs[kq + 3][m] = vb.w;
        }
        __syncthreads();

#pragma unroll
        for (int k = 0; k < 16; k++) {
            float a[8], b[8];
            *(float4*)&a[0] = *(const float4*)&As[k][ty * 8];
            *(float4*)&a[4] = *(const float4*)&As[k][ty * 8 + 4];
            *(float4*)&b[0] = *(const float4*)&Bs[k][tx * 8];
            *(float4*)&b[4] = *(const float4*)&Bs[k][tx * 8 + 4];
#pragma unroll
            for (int i = 0; i < 8; i++)
#pragma unroll
                for (int j = 0; j < 8; j++)
                    acc[i][j] += a[i] * b[j];
        }
        __syncthreads();
    }

#pragma unroll
    for (int i = 0; i < 8; i++) {
        int r = row0 + ty * 8 + i;
#pragma unroll
        for (int j4 = 0; j4 < 8; j4 += 4) {
            int c = col0 + tx * 8 + j4;
            float4 o;
            o.x = acc[i][j4 + 0]; o.y = acc[i][j4 + 1];
            o.z = acc[i][j4 + 2]; o.w = acc[i][j4 + 3];
            if (bias) {
                o.x += bias[c]; o.y += bias[c + 1];
                o.z += bias[c + 2]; o.w += bias[c + 3];
            }
            *(float4*)(C + (size_t)r * KDIM + c) = o;
        }
    }
}

// ---------------------------------------------------------------------------
// Flash-style attention. One block = one (b, h, 64-query tile).
// 256 threads: tr = tid>>4 owns query rows tr*4..+3; tc = tid&15 owns cols
// (keys for S, head-dims for O) tc*4..+3.
// KPs is a union: first holds K transposed [d][key] with XOR swizzle
// (conflict-free, no padding), then reused for P = exp(S-m).
// ---------------------------------------------------------------------------
__global__ __launch_bounds__(256) void attn_kernel()
{
    __shared__ __align__(16) float Qs[64][64];   // [q_row][d], pre-scaled
    __shared__ __align__(16) float Vs[64][64];   // [key][d_out]
    __shared__ __align__(16) float KPs[64 * 64]; // union: Kt swizzled / P

    const int tid = threadIdx.x;
    const int tr = tid >> 4;
    const int tc = tid & 15;
    const int qt = blockIdx.x;       // 0..31
    const int bh = blockIdx.y;       // 0..63
    const int b = bh >> 4;
    const int h = bh & 15;

    const float scale = 0.03125f;    // 1/sqrt(1024)

    const float* qbase  = g_q + ((size_t)(b * TLEN + qt * 64)) * KDIM + h * HS;
    const float* kbase0 = g_k + ((size_t)(b * TLEN)) * KDIM + h * HS;
    const float* vbase0 = g_v + ((size_t)(b * TLEN)) * KDIM + h * HS;

    // Load Q tile (scale folded in)
#pragma unroll
    for (int it = 0; it < 4; it++) {
        int idx = it * 256 + tid;
        int r  = idx >> 4;
        int dq = (idx & 15) << 2;
        float4 v = *(const float4*)(qbase + (size_t)r * KDIM + dq);
        v.x *= scale; v.y *= scale; v.z *= scale; v.w *= scale;
        *(float4*)&Qs[r][dq] = v;
    }

    float m[4], l[4], o[4][4];
#pragma unroll
    for (int i = 0; i < 4; i++) {
        m[i] = -1e30f; l[i] = 0.f;
#pragma unroll
        for (int j = 0; j < 4; j++) o[i][j] = 0.f;
    }

    for (int kt = 0; kt < 32; kt++) {
        __syncthreads();  // prior iteration's Vs/KPs reads done
        const float* kbase = kbase0 + (size_t)kt * 64 * KDIM;
        const float* vbase = vbase0 + (size_t)kt * 64 * KDIM;

        // Load K (transposed + swizzled) and V tiles
#pragma unroll
        for (int it = 0; it < 4; it++) {
            int idx = it * 256 + tid;
            int kk = idx >> 4;           // key index
            int dq = (idx & 15) << 2;    // d chunk
            float4 kv = *(const float4*)(kbase + (size_t)kk * KDIM + dq);
            int c4 = kk >> 2, cl = kk & 3;
            KPs[(dq + 0) * 64 + (((c4 ^ ((dq + 0) & 15)) << 2) | cl)] = kv.x;
            KPs[(dq + 1) * 64 + (((c4 ^ ((dq + 1) & 15)) << 2) | cl)] = kv.y;
            KPs[(dq + 2) * 64 + (((c4 ^ ((dq + 2) & 15)) << 2) | cl)] = kv.z;
            KPs[(dq + 3) * 64 + (((c4 ^ ((dq + 3) & 15)) << 2) | cl)] = kv.w;
            *(float4*)&Vs[kk][dq] = *(const float4*)(vbase + (size_t)kk * KDIM + dq);
        }
        __syncthreads();

        // S = (Q*scale) @ K^T  (4x4 per thread)
        float s[4][4];
#pragma unroll
        for (int i = 0; i < 4; i++)
#pragma unroll
            for (int j = 0; j < 4; j++) s[i][j] = 0.f;

#pragma unroll
        for (int d0 = 0; d0 < 64; d0 += 4) {
            float ka[4][4];
#pragma unroll
            for (int u = 0; u < 4; u++) {
                int d = d0 + u;
                float4 t = *(const float4*)&KPs[d * 64 + ((tc ^ (d & 15)) << 2)];
                ka[u][0] = t.x; ka[u][1] = t.y; ka[u][2] = t.z; ka[u][3] = t.w;
            }
#pragma unroll
            for (int i = 0; i < 4; i++) {
                float4 qv = *(const float4*)&Qs[(tr << 2) + i][d0];
                float qa[4] = {qv.x, qv.y, qv.z, qv.w};
#pragma unroll
                for (int u = 0; u < 4; u++)
#pragma unroll
                    for (int j = 0; j < 4; j++)
                        s[i][j] += qa[u] * ka[u][j];
            }
        }

        // Online softmax update
        float p[4][4];
#pragma unroll
        for (int i = 0; i < 4; i++) {
            float mm = fmaxf(fmaxf(s[i][0], s[i][1]), fmaxf(s[i][2], s[i][3]));
            mm = fmaxf(mm, __shfl_xor_sync(0xffffffffu, mm, 8));
            mm = fmaxf(mm, __shfl_xor_sync(0xffffffffu, mm, 4));
            mm = fmaxf(mm, __shfl_xor_sync(0xffffffffu, mm, 2));
            mm = fmaxf(mm, __shfl_xor_sync(0xffffffffu, mm, 1));
            float mnew = fmaxf(m[i], mm);
            float alpha = __expf(m[i] - mnew);
            m[i] = mnew;
            float lloc = 0.f;
#pragma unroll
            for (int j = 0; j < 4; j++) {
                p[i][j] = __expf(s[i][j] - mnew);
                lloc += p[i][j];
            }
            lloc += __shfl_xor_sync(0xffffffffu, lloc, 8);
            lloc += __shfl_xor_sync(0xffffffffu, lloc, 4);
            lloc += __shfl_xor_sync(0xffffffffu, lloc, 2);
            lloc += __shfl_xor_sync(0xffffffffu, lloc, 1);
            l[i] = l[i] * alpha + lloc;
#pragma unroll
            for (int j = 0; j < 4; j++) o[i][j] *= alpha;
        }

        __syncthreads();  // everyone done reading K from KPs
        // Write P (plain row-major, keys contiguous)
#pragma unroll
        for (int i = 0; i < 4; i++) {
            float4 pv;
            pv.x = p[i][0]; pv.y = p[i][1]; pv.z = p[i][2]; pv.w = p[i][3];
            *(float4*)&KPs[((tr << 2) + i) * 64 + (tc << 2)] = pv;
        }
        __syncthreads();

        // O += P @ V
#pragma unroll
        for (int k0 = 0; k0 < 64; k0 += 4) {
            float va[4][4];
#pragma unroll
            for (int u = 0; u < 4; u++) {
                float4 t = *(const float4*)&Vs[k0 + u][tc << 2];
                va[u][0] = t.x; va[u][1] = t.y; va[u][2] = t.z; va[u][3] = t.w;
            }
#pragma unroll
            for (int i = 0; i < 4; i++) {
                float4 pv = *(const float4*)&KPs[((tr << 2) + i) * 64 + k0];
                float pa[4] = {pv.x, pv.y, pv.z, pv.w};
#pragma unroll
                for (int u = 0; u < 4; u++)
#pragma unroll
                    for (int j = 0; j < 4; j++)
                        o[i][j] += pa[u] * va[u][j];
            }
        }
    }

    // Normalize + store
    float* obase = g_attn + ((size_t)(b * TLEN + qt * 64)) * KDIM + h * HS;
#pragma unroll
    for (int i = 0; i < 4; i++) {
        float inv = 1.f / l[i];
        float4 ov;
        ov.x = o[i][0] * inv; ov.y = o[i][1] * inv;
        ov.z = o[i][2] * inv; ov.w = o[i][3] * inv;
        *(float4*)(obase + (size_t)((tr << 2) + i) * KDIM + (tc << 2)) = ov;
    }
}

// ---------------------------------------------------------------------------
extern "C" void kernel_launch(void* const* d_in, const int* in_sizes, int n_in,
                              void* d_out, int out_size)
{
    const float* x  = (const float*)d_in[0];
    const float* Wk = (const float*)d_in[1];
    const float* Wq = (const float*)d_in[2];
    const float* Wv = (const float*)d_in[3];
    const float* Wu = (const float*)d_in[4];
    const float* bu = (const float*)d_in[5];
    float* out = (float*)d_out;

    dim3 gg(KDIM / 128, MROWS / 128);   // (8, 64)
    gemm_nt<<<gg, 256>>>(x, Wq, nullptr, nullptr, 0);
    gemm_nt<<<gg, 256>>>(x, Wk, nullptr, nullptr, 1);
    gemm_nt<<<gg, 256>>>(x, Wv, nullptr, nullptr, 2);
    attn_kernel<<<dim3(32, 64), 256>>>();
    gemm_nt<<<gg, 256>>>(nullptr, Wu, bu, out, 3);
}

// round 4
// speedup vs baseline: 1.3338x; 1.3338x over previous
#include <cuda_runtime.h>
#include <cuda_bf16.h>
#include <cstdint>
#include <math.h>

#define MROWS 8192   // B*T
#define KDIM  1024
#define TLEN  2048
#define HS    64

// ---------------- Scratch (device globals; alloc-free rule) ----------------
__device__ float g_q[MROWS * KDIM];
__device__ float g_k[MROWS * KDIM];
__device__ float g_v[MROWS * KDIM];
__device__ float g_attn[MROWS * KDIM];
__device__ __nv_bfloat16 g_ahi[MROWS * KDIM];      // activation hi/lo
__device__ __nv_bfloat16 g_alo[MROWS * KDIM];
__device__ __nv_bfloat16 g_whi[4 * KDIM * KDIM];   // Wq,Wk,Wv,Wu hi
__device__ __nv_bfloat16 g_wlo[4 * KDIM * KDIM];   // lo

// ---------------- helpers ----------------
__device__ __forceinline__ uint32_t smem_u32(const void* p) {
    uint32_t a;
    asm("{ .reg .u64 t; cvta.to.shared.u64 t, %1; cvt.u32.u64 %0, t; }"
        : "=r"(a) : "l"(p));
    return a;
}

__device__ __forceinline__ void cp16(uint32_t dst, const void* src) {
    asm volatile("cp.async.cg.shared.global [%0], [%1], 16;" :: "r"(dst), "l"(src));
}

__device__ __forceinline__ void ldm_x4(uint32_t* r, uint32_t addr) {
    asm volatile("ldmatrix.sync.aligned.m8n8.x4.shared.b16 {%0,%1,%2,%3}, [%4];"
                 : "=r"(r[0]), "=r"(r[1]), "=r"(r[2]), "=r"(r[3]) : "r"(addr));
}

__device__ __forceinline__ void mma16816(float* c, const uint32_t* a,
                                         uint32_t b0, uint32_t b1) {
    asm volatile(
        "mma.sync.aligned.m16n8k16.row.col.f32.bf16.bf16.f32 "
        "{%0,%1,%2,%3}, {%4,%5,%6,%7}, {%8,%9}, {%0,%1,%2,%3};"
        : "+f"(c[0]), "+f"(c[1]), "+f"(c[2]), "+f"(c[3])
        : "r"(a[0]), "r"(a[1]), "r"(a[2]), "r"(a[3]), "r"(b0), "r"(b1));
}

// ---------------------------------------------------------------------------
// Split fp32 -> bf16 hi + lo (bf16x3 decomposition)
// ---------------------------------------------------------------------------
__global__ __launch_bounds__(256) void split_bf16(const float* __restrict__ src,
                                                  __nv_bfloat16* __restrict__ hi,
                                                  __nv_bfloat16* __restrict__ lo,
                                                  int n4)
{
    int i = blockIdx.x * blockDim.x + threadIdx.x;
    if (i >= n4) return;
    float4 v = ((const float4*)src)[i];
    __nv_bfloat16 h0 = __float2bfloat16_rn(v.x);
    __nv_bfloat16 h1 = __float2bfloat16_rn(v.y);
    __nv_bfloat16 h2 = __float2bfloat16_rn(v.z);
    __nv_bfloat16 h3 = __float2bfloat16_rn(v.w);
    __nv_bfloat16 l0 = __float2bfloat16_rn(v.x - __bfloat162float(h0));
    __nv_bfloat16 l1 = __float2bfloat16_rn(v.y - __bfloat162float(h1));
    __nv_bfloat16 l2 = __float2bfloat16_rn(v.z - __bfloat162float(h2));
    __nv_bfloat16 l3 = __float2bfloat16_rn(v.w - __bfloat162float(h3));
    __nv_bfloat162 hp0 = {h0, h1}, hp1 = {h2, h3};
    __nv_bfloat162 lp0 = {l0, l1}, lp1 = {l2, l3};
    uint2 hu, lu;
    hu.x = *(uint32_t*)&hp0; hu.y = *(uint32_t*)&hp1;
    lu.x = *(uint32_t*)&lp0; lu.y = *(uint32_t*)&lp1;
    ((uint2*)hi)[i] = hu;
    ((uint2*)lo)[i] = lu;
}

// ---------------------------------------------------------------------------
// mma.sync bf16x3 GEMM: C = A @ B^T (+bias). A:(8192,1024) B:(1024,1024) K-major.
// 128x128 tile / CTA, K-chunk 32, 2-stage cp.async. 8 warps: 2(M) x 4(N),
// warp tile 64x32, m16n8k16 fragments. 3 MMAs per tile for the hi/lo split.
// ---------------------------------------------------------------------------
#define BKC      32
#define ROWE     40                  // bf16 per smem row (32 data + 8 pad)
#define ROWB     80                  // bytes per smem row
#define TILE_SB  (128 * ROWB)        // 10240 B
#define STAGE_SB (4 * TILE_SB)       // Ahi | Alo | Bhi | Blo = 40960 B
#define SMEM_REQ (2 * STAGE_SB)      // 81920 B

__global__ __launch_bounds__(256) void gemm_mma(
    const __nv_bfloat16* __restrict__ Ahi, const __nv_bfloat16* __restrict__ Alo,
    const __nv_bfloat16* __restrict__ Bhi, const __nv_bfloat16* __restrict__ Blo,
    float* __restrict__ C, const float* __restrict__ bias)
{
    extern __shared__ char smem_raw[];
    const uint32_t sbase = smem_u32(smem_raw);

    const int tid  = threadIdx.x;
    const int wid  = tid >> 5;
    const int lane = tid & 31;
    const int wm   = wid >> 2;        // 0..1
    const int wn   = wid & 3;         // 0..3
    const int row0 = blockIdx.y * 128;
    const int col0 = blockIdx.x * 128;

    float acc[4][4][4];
#pragma unroll
    for (int i = 0; i < 4; i++)
#pragma unroll
        for (int j = 0; j < 4; j++)
#pragma unroll
            for (int t = 0; t < 4; t++) acc[i][j][t] = 0.f;

    auto load_chunk = [&](int c) {
        uint32_t st = sbase + (uint32_t)(c & 1) * STAGE_SB;
        int k0 = c * BKC;
#pragma unroll
        for (int it = 0; it < 2; it++) {
            int idx = it * 256 + tid;          // 0..511
            int r   = idx >> 2;                // 0..127
            int cb  = (idx & 3) << 4;          // 0,16,32,48 bytes
            uint32_t so = (uint32_t)(r * ROWB + cb);
            cp16(st + so,               (const char*)(Ahi + (size_t)(row0 + r) * KDIM + k0) + cb);
            cp16(st + TILE_SB + so,     (const char*)(Alo + (size_t)(row0 + r) * KDIM + k0) + cb);
            cp16(st + 2 * TILE_SB + so, (const char*)(Bhi + (size_t)(col0 + r) * KDIM + k0) + cb);
            cp16(st + 3 * TILE_SB + so, (const char*)(Blo + (size_t)(col0 + r) * KDIM + k0) + cb);
        }
        asm volatile("cp.async.commit_group;" ::: "memory");
    };

    load_chunk(0);
    load_chunk(1);

    const int NCHUNK = KDIM / BKC;    // 32
    const int lr = lane & 15;         // ldmatrix row within 16
    const int lc = lane >> 4;         // k-half selector

    for (int c = 0; c < NCHUNK; c++) {
        if (c == NCHUNK - 1) asm volatile("cp.async.wait_group 0;" ::: "memory");
        else                 asm volatile("cp.async.wait_group 1;" ::: "memory");
        __syncthreads();

        uint32_t st = sbase + (uint32_t)(c & 1) * STAGE_SB;
        uint32_t aBase = st + (uint32_t)((wm * 64 + lr) * ROWB);
        uint32_t bBase = st + 2 * TILE_SB + (uint32_t)((wn * 32 + lr) * ROWB);

#pragma unroll
        for (int ks = 0; ks < BKC; ks += 16) {
            uint32_t colb = (uint32_t)((ks + 8 * lc) * 2);
            uint32_t ah[4][4], al[4][4], bh[2][4], bl[2][4];
#pragma unroll
            for (int mi = 0; mi < 4; mi++) {
                uint32_t ad = aBase + (uint32_t)(mi * 16 * ROWB) + colb;
                ldm_x4(ah[mi], ad);
                ldm_x4(al[mi], ad + TILE_SB);
            }
#pragma unroll
            for (int nj = 0; nj < 2; nj++) {
                uint32_t bd = bBase + (uint32_t)(nj * 16 * ROWB) + colb;
                ldm_x4(bh[nj], bd);
                ldm_x4(bl[nj], bd + TILE_SB);
            }
#pragma unroll
            for (int mi = 0; mi < 4; mi++)
#pragma unroll
                for (int ni = 0; ni < 4; ni++) {
                    int nj = ni >> 1, s = ni & 1;
                    mma16816(acc[mi][ni], ah[mi], bh[nj][s], bh[nj][s + 2]);
                    mma16816(acc[mi][ni], ah[mi], bl[nj][s], bl[nj][s + 2]);
                    mma16816(acc[mi][ni], al[mi], bh[nj][s], bh[nj][s + 2]);
                }
        }
        __syncthreads();
        if (c + 2 < NCHUNK) load_chunk(c + 2);
    }

    // Epilogue: fragment c layout -> rows (lane>>2, +8), cols 2*(lane&3)
#pragma unroll
    for (int ni = 0; ni < 4; ni++) {
        int col = col0 + wn * 32 + ni * 8 + 2 * (lane & 3);
        float b0 = bias ? bias[col] : 0.f;
        float b1 = bias ? bias[col + 1] : 0.f;
#pragma unroll
        for (int mi = 0; mi < 4; mi++) {
            int r0 = row0 + wm * 64 + mi * 16 + (lane >> 2);
            float2 v0, v1;
            v0.x = acc[mi][ni][0] + b0; v0.y = acc[mi][ni][1] + b1;
            v1.x = acc[mi][ni][2] + b0; v1.y = acc[mi][ni][3] + b1;
            *(float2*)(C + (size_t)r0 * KDIM + col) = v0;
            *(float2*)(C + (size_t)(r0 + 8) * KDIM + col) = v1;
        }
    }
}

// ---------------------------------------------------------------------------
// Flash-style attention (unchanged known-passing fp32 kernel)
// ---------------------------------------------------------------------------
__global__ __launch_bounds__(256) void attn_kernel()
{
    __shared__ __align__(16) float Qs[64][64];
    __shared__ __align__(16) float Vs[64][64];
    __shared__ __align__(16) float KPs[64 * 64];

    const int tid = threadIdx.x;
    const int tr = tid >> 4;
    const int tc = tid & 15;
    const int qt = blockIdx.x;
    const int bh = blockIdx.y;
    const int b = bh >> 4;
    const int h = bh & 15;

    const float scale = 0.03125f;

    const float* qbase  = g_q + ((size_t)(b * TLEN + qt * 64)) * KDIM + h * HS;
    const float* kbase0 = g_k + ((size_t)(b * TLEN)) * KDIM + h * HS;
    const float* vbase0 = g_v + ((size_t)(b * TLEN)) * KDIM + h * HS;

#pragma unroll
    for (int it = 0; it < 4; it++) {
        int idx = it * 256 + tid;
        int r  = idx >> 4;
        int dq = (idx & 15) << 2;
        float4 v = *(const float4*)(qbase + (size_t)r * KDIM + dq);
        v.x *= scale; v.y *= scale; v.z *= scale; v.w *= scale;
        *(float4*)&Qs[r][dq] = v;
    }

    float m[4], l[4], o[4][4];
#pragma unroll
    for (int i = 0; i < 4; i++) {
        m[i] = -1e30f; l[i] = 0.f;
#pragma unroll
        for (int j = 0; j < 4; j++) o[i][j] = 0.f;
    }

    for (int kt = 0; kt < 32; kt++) {
        __syncthreads();
        const float* kbase = kbase0 + (size_t)kt * 64 * KDIM;
        const float* vbase = vbase0 + (size_t)kt * 64 * KDIM;

#pragma unroll
        for (int it = 0; it < 4; it++) {
            int idx = it * 256 + tid;
            int kk = idx >> 4;
            int dq = (idx & 15) << 2;
            float4 kv = *(const float4*)(kbase + (size_t)kk * KDIM + dq);
            int c4 = kk >> 2, cl = kk & 3;
            KPs[(dq + 0) * 64 + (((c4 ^ ((dq + 0) & 15)) << 2) | cl)] = kv.x;
            KPs[(dq + 1) * 64 + (((c4 ^ ((dq + 1) & 15)) << 2) | cl)] = kv.y;
            KPs[(dq + 2) * 64 + (((c4 ^ ((dq + 2) & 15)) << 2) | cl)] = kv.z;
            KPs[(dq + 3) * 64 + (((c4 ^ ((dq + 3) & 15)) << 2) | cl)] = kv.w;
            *(float4*)&Vs[kk][dq] = *(const float4*)(vbase + (size_t)kk * KDIM + dq);
        }
        __syncthreads();

        float s[4][4];
#pragma unroll
        for (int i = 0; i < 4; i++)
#pragma unroll
            for (int j = 0; j < 4; j++) s[i][j] = 0.f;

#pragma unroll
        for (int d0 = 0; d0 < 64; d0 += 4) {
            float ka[4][4];
#pragma unroll
            for (int u = 0; u < 4; u++) {
                int d = d0 + u;
                float4 t = *(const float4*)&KPs[d * 64 + ((tc ^ (d & 15)) << 2)];
                ka[u][0] = t.x; ka[u][1] = t.y; ka[u][2] = t.z; ka[u][3] = t.w;
            }
#pragma unroll
            for (int i = 0; i < 4; i++) {
                float4 qv = *(const float4*)&Qs[(tr << 2) + i][d0];
                float qa[4] = {qv.x, qv.y, qv.z, qv.w};
#pragma unroll
                for (int u = 0; u < 4; u++)
#pragma unroll
                    for (int j = 0; j < 4; j++)
                        s[i][j] += qa[u] * ka[u][j];
            }
        }

        float p[4][4];
#pragma unroll
        for (int i = 0; i < 4; i++) {
            float mm = fmaxf(fmaxf(s[i][0], s[i][1]), fmaxf(s[i][2], s[i][3]));
            mm = fmaxf(mm, __shfl_xor_sync(0xffffffffu, mm, 8));
            mm = fmaxf(mm, __shfl_xor_sync(0xffffffffu, mm, 4));
            mm = fmaxf(mm, __shfl_xor_sync(0xffffffffu, mm, 2));
            mm = fmaxf(mm, __shfl_xor_sync(0xffffffffu, mm, 1));
            float mnew = fmaxf(m[i], mm);
            float alpha = __expf(m[i] - mnew);
            m[i] = mnew;
            float lloc = 0.f;
#pragma unroll
            for (int j = 0; j < 4; j++) {
                p[i][j] = __expf(s[i][j] - mnew);
                lloc += p[i][j];
            }
            lloc += __shfl_xor_sync(0xffffffffu, lloc, 8);
            lloc += __shfl_xor_sync(0xffffffffu, lloc, 4);
            lloc += __shfl_xor_sync(0xffffffffu, lloc, 2);
            lloc += __shfl_xor_sync(0xffffffffu, lloc, 1);
            l[i] = l[i] * alpha + lloc;
#pragma unroll
            for (int j = 0; j < 4; j++) o[i][j] *= alpha;
        }

        __syncthreads();
#pragma unroll
        for (int i = 0; i < 4; i++) {
            float4 pv;
            pv.x = p[i][0]; pv.y = p[i][1]; pv.z = p[i][2]; pv.w = p[i][3];
            *(float4*)&KPs[((tr << 2) + i) * 64 + (tc << 2)] = pv;
        }
        __syncthreads();

#pragma unroll
        for (int k0 = 0; k0 < 64; k0 += 4) {
            float va[4][4];
#pragma unroll
            for (int u = 0; u < 4; u++) {
                float4 t = *(const float4*)&Vs[k0 + u][tc << 2];
                va[u][0] = t.x; va[u][1] = t.y; va[u][2] = t.z; va[u][3] = t.w;
            }
#pragma unroll
            for (int i = 0; i < 4; i++) {
                float4 pv = *(const float4*)&KPs[((tr << 2) + i) * 64 + k0];
                float pa[4] = {pv.x, pv.y, pv.z, pv.w};
#pragma unroll
                for (int u = 0; u < 4; u++)
#pragma unroll
                    for (int j = 0; j < 4; j++)
                        o[i][j] += pa[u] * va[u][j];
            }
        }
    }

    float* obase = g_attn + ((size_t)(b * TLEN + qt * 64)) * KDIM + h * HS;
#pragma unroll
    for (int i = 0; i < 4; i++) {
        float inv = 1.f / l[i];
        float4 ov;
        ov.x = o[i][0] * inv; ov.y = o[i][1] * inv;
        ov.z = o[i][2] * inv; ov.w = o[i][3] * inv;
        *(float4*)(obase + (size_t)((tr << 2) + i) * KDIM + (tc << 2)) = ov;
    }
}

// ---------------------------------------------------------------------------
extern "C" void kernel_launch(void* const* d_in, const int* in_sizes, int n_in,
                              void* d_out, int out_size)
{
    const float* x  = (const float*)d_in[0];
    const float* Wk = (const float*)d_in[1];
    const float* Wq = (const float*)d_in[2];
    const float* Wv = (const float*)d_in[3];
    const float* Wu = (const float*)d_in[4];
    const float* bu = (const float*)d_in[5];
    float* out = (float*)d_out;

    cudaFuncSetAttribute(gemm_mma, cudaFuncAttributeMaxDynamicSharedMemorySize, SMEM_REQ);

    __nv_bfloat16 *ahi, *alo, *whi, *wlo;
    cudaGetSymbolAddress((void**)&ahi, g_ahi);
    cudaGetSymbolAddress((void**)&alo, g_alo);
    cudaGetSymbolAddress((void**)&whi, g_whi);
    cudaGetSymbolAddress((void**)&wlo, g_wlo);
    float *gq, *gk, *gv, *gat;
    cudaGetSymbolAddress((void**)&gq, g_q);
    cudaGetSymbolAddress((void**)&gk, g_k);
    cudaGetSymbolAddress((void**)&gv, g_v);
    cudaGetSymbolAddress((void**)&gat, g_attn);

    const int nx4 = MROWS * KDIM / 4;
    const int nw4 = KDIM * KDIM / 4;
    const size_t WSZ = (size_t)KDIM * KDIM;

    split_bf16<<<nx4 / 256, 256>>>(x, ahi, alo, nx4);
    split_bf16<<<nw4 / 256, 256>>>(Wq, whi + 0 * WSZ, wlo + 0 * WSZ, nw4);
    split_bf16<<<nw4 / 256, 256>>>(Wk, whi + 1 * WSZ, wlo + 1 * WSZ, nw4);
    split_bf16<<<nw4 / 256, 256>>>(Wv, whi + 2 * WSZ, wlo + 2 * WSZ, nw4);
    split_bf16<<<nw4 / 256, 256>>>(Wu, whi + 3 * WSZ, wlo + 3 * WSZ, nw4);

    dim3 gg(KDIM / 128, MROWS / 128);   // (8, 64)
    gemm_mma<<<gg, 256, SMEM_REQ>>>(ahi, alo, whi + 0 * WSZ, wlo + 0 * WSZ, gq, nullptr);
    gemm_mma<<<gg, 256, SMEM_REQ>>>(ahi, alo, whi + 1 * WSZ, wlo + 1 * WSZ, gk, nullptr);
    gemm_mma<<<gg, 256, SMEM_REQ>>>(ahi, alo, whi + 2 * WSZ, wlo + 2 * WSZ, gv, nullptr);

    attn_kernel<<<dim3(32, 64), 256>>>();

    split_bf16<<<nx4 / 256, 256>>>(gat, ahi, alo, nx4);
    gemm_mma<<<gg, 256, SMEM_REQ>>>(ahi, alo, whi + 3 * WSZ, wlo + 3 * WSZ, out, bu);
}

// round 5
// speedup vs baseline: 2.3741x; 1.7800x over previous
#include <cuda_runtime.h>
#include <cuda_bf16.h>
#include <cstdint>
#include <math.h>

#define MROWS 8192   // B*T
#define KDIM  1024
#define TLEN  2048
#define HS    64

// ---------------- Scratch (device globals; alloc-free rule) ----------------
__device__ __nv_bfloat16 g_ahi[MROWS * KDIM];      // x hi/lo, later attn-out hi/lo
__device__ __nv_bfloat16 g_alo[MROWS * KDIM];
__device__ __nv_bfloat16 g_whi[4 * KDIM * KDIM];   // Wq,Wk,Wv,Wu hi
__device__ __nv_bfloat16 g_wlo[4 * KDIM * KDIM];   // lo
__device__ __nv_bfloat16 g_qh[MROWS * KDIM];
__device__ __nv_bfloat16 g_ql[MROWS * KDIM];
__device__ __nv_bfloat16 g_kh[MROWS * KDIM];
__device__ __nv_bfloat16 g_kl[MROWS * KDIM];
__device__ __nv_bfloat16 g_vh[MROWS * KDIM];
__device__ __nv_bfloat16 g_vl[MROWS * KDIM];

// ---------------- helpers ----------------
__device__ __forceinline__ uint32_t smem_u32(const void* p) {
    uint32_t a;
    asm("{ .reg .u64 t; cvta.to.shared.u64 t, %1; cvt.u32.u64 %0, t; }"
        : "=r"(a) : "l"(p));
    return a;
}

__device__ __forceinline__ void cp16(uint32_t dst, const void* src) {
    asm volatile("cp.async.cg.shared.global [%0], [%1], 16;" :: "r"(dst), "l"(src));
}

__device__ __forceinline__ void ldm_x4(uint32_t* r, uint32_t addr) {
    asm volatile("ldmatrix.sync.aligned.m8n8.x4.shared.b16 {%0,%1,%2,%3}, [%4];"
                 : "=r"(r[0]), "=r"(r[1]), "=r"(r[2]), "=r"(r[3]) : "r"(addr));
}

__device__ __forceinline__ void ldm_x4t(uint32_t* r, uint32_t addr) {
    asm volatile("ldmatrix.sync.aligned.m8n8.x4.trans.shared.b16 {%0,%1,%2,%3}, [%4];"
                 : "=r"(r[0]), "=r"(r[1]), "=r"(r[2]), "=r"(r[3]) : "r"(addr));
}

__device__ __forceinline__ void mma16816(float* c, const uint32_t* a,
                                         uint32_t b0, uint32_t b1) {
    asm volatile(
        "mma.sync.aligned.m16n8k16.row.col.f32.bf16.bf16.f32 "
        "{%0,%1,%2,%3}, {%4,%5,%6,%7}, {%8,%9}, {%0,%1,%2,%3};"
        : "+f"(c[0]), "+f"(c[1]), "+f"(c[2]), "+f"(c[3])
        : "r"(a[0]), "r"(a[1]), "r"(a[2]), "r"(a[3]), "r"(b0), "r"(b1));
}

// pack two floats into bf16 hi pair + residual lo pair
__device__ __forceinline__ void pack_hl(float x, float y, uint32_t& h, uint32_t& l) {
    __nv_bfloat162 hp = __floats2bfloat162_rn(x, y);
    float rx = x - __bfloat162float(hp.x);
    float ry = y - __bfloat162float(hp.y);
    __nv_bfloat162 lp = __floats2bfloat162_rn(rx, ry);
    h = *(uint32_t*)&hp;
    l = *(uint32_t*)&lp;
}

// ---------------------------------------------------------------------------
// Split fp32 -> bf16 hi + lo
// ---------------------------------------------------------------------------
__global__ __launch_bounds__(256) void split_bf16(const float* __restrict__ src,
                                                  __nv_bfloat16* __restrict__ hi,
                                                  __nv_bfloat16* __restrict__ lo,
                                                  int n4)
{
    int i = blockIdx.x * blockDim.x + threadIdx.x;
    if (i >= n4) return;
    float4 v = ((const float4*)src)[i];
    uint32_t h0, l0, h1, l1;
    pack_hl(v.x, v.y, h0, l0);
    pack_hl(v.z, v.w, h1, l1);
    uint2 hu = {h0, h1}, lu = {l0, l1};
    ((uint2*)hi)[i] = hu;
    ((uint2*)lo)[i] = lu;
}

// ---------------------------------------------------------------------------
// mma.sync bf16x3 GEMM: C = A @ B^T. A:(8192,1024), B:(1024,1024), K-major.
// 128x128 / CTA, K-chunk 32, 2-stage cp.async, 8 warps (2x4), warp 64x32.
// Output: either fp32 (+bias) to Cf, or bf16 hi/lo split to Chi/Clo.
// ---------------------------------------------------------------------------
#define BKC      32
#define ROWB     80                  // bytes per smem row (64 data + 16 pad)
#define TILE_SB  (128 * ROWB)
#define STAGE_SB (4 * TILE_SB)
#define SMEM_REQ (2 * STAGE_SB)      // 81920 B

__global__ __launch_bounds__(256) void gemm_mma(
    const __nv_bfloat16* __restrict__ Ahi, const __nv_bfloat16* __restrict__ Alo,
    const __nv_bfloat16* __restrict__ Bhi, const __nv_bfloat16* __restrict__ Blo,
    float* __restrict__ Cf, const float* __restrict__ bias,
    __nv_bfloat16* __restrict__ Chi, __nv_bfloat16* __restrict__ Clo)
{
    extern __shared__ char smem_raw[];
    const uint32_t sbase = smem_u32(smem_raw);

    const int tid  = threadIdx.x;
    const int wid  = tid >> 5;
    const int lane = tid & 31;
    const int wm   = wid >> 2;
    const int wn   = wid & 3;
    const int row0 = blockIdx.y * 128;
    const int col0 = blockIdx.x * 128;

    float acc[4][4][4];
#pragma unroll
    for (int i = 0; i < 4; i++)
#pragma unroll
        for (int j = 0; j < 4; j++)
#pragma unroll
            for (int t = 0; t < 4; t++) acc[i][j][t] = 0.f;

    auto load_chunk = [&](int c) {
        uint32_t st = sbase + (uint32_t)(c & 1) * STAGE_SB;
        int k0 = c * BKC;
#pragma unroll
        for (int it = 0; it < 2; it++) {
            int idx = it * 256 + tid;
            int r   = idx >> 2;
            int cb  = (idx & 3) << 4;
            uint32_t so = (uint32_t)(r * ROWB + cb);
            cp16(st + so,               (const char*)(Ahi + (size_t)(row0 + r) * KDIM + k0) + cb);
            cp16(st + TILE_SB + so,     (const char*)(Alo + (size_t)(row0 + r) * KDIM + k0) + cb);
            cp16(st + 2 * TILE_SB + so, (const char*)(Bhi + (size_t)(col0 + r) * KDIM + k0) + cb);
            cp16(st + 3 * TILE_SB + so, (const char*)(Blo + (size_t)(col0 + r) * KDIM + k0) + cb);
        }
        asm volatile("cp.async.commit_group;" ::: "memory");
    };

    load_chunk(0);
    load_chunk(1);

    const int NCHUNK = KDIM / BKC;
    const int lr = lane & 15;
    const int lc = lane >> 4;

    for (int c = 0; c < NCHUNK; c++) {
        if (c == NCHUNK - 1) asm volatile("cp.async.wait_group 0;" ::: "memory");
        else                 asm volatile("cp.async.wait_group 1;" ::: "memory");
        __syncthreads();

        uint32_t st = sbase + (uint32_t)(c & 1) * STAGE_SB;
        uint32_t aBase = st + (uint32_t)((wm * 64 + lr) * ROWB);
        uint32_t bBase = st + 2 * TILE_SB + (uint32_t)((wn * 32 + lr) * ROWB);

#pragma unroll
        for (int ks = 0; ks < BKC; ks += 16) {
            uint32_t colb = (uint32_t)((ks + 8 * lc) * 2);
            uint32_t ah[4][4], al[4][4], bh[2][4], bl[2][4];
#pragma unroll
            for (int mi = 0; mi < 4; mi++) {
                uint32_t ad = aBase + (uint32_t)(mi * 16 * ROWB) + colb;
                ldm_x4(ah[mi], ad);
                ldm_x4(al[mi], ad + TILE_SB);
            }
#pragma unroll
            for (int nj = 0; nj < 2; nj++) {
                uint32_t bd = bBase + (uint32_t)(nj * 16 * ROWB) + colb;
                ldm_x4(bh[nj], bd);
                ldm_x4(bl[nj], bd + TILE_SB);
            }
#pragma unroll
            for (int mi = 0; mi < 4; mi++)
#pragma unroll
                for (int ni = 0; ni < 4; ni++) {
                    int nj = ni >> 1, s = ni & 1;
                    mma16816(acc[mi][ni], ah[mi], bh[nj][s], bh[nj][s + 2]);
                    mma16816(acc[mi][ni], ah[mi], bl[nj][s], bl[nj][s + 2]);
                    mma16816(acc[mi][ni], al[mi], bh[nj][s], bh[nj][s + 2]);
                }
        }
        __syncthreads();
        if (c + 2 < NCHUNK) load_chunk(c + 2);
    }

#pragma unroll
    for (int ni = 0; ni < 4; ni++) {
        int col = col0 + wn * 32 + ni * 8 + 2 * (lane & 3);
#pragma unroll
        for (int mi = 0; mi < 4; mi++) {
            int r0 = row0 + wm * 64 + mi * 16 + (lane >> 2);
            if (Cf) {
                float b0 = bias ? bias[col] : 0.f;
                float b1 = bias ? bias[col + 1] : 0.f;
                float2 v0 = {acc[mi][ni][0] + b0, acc[mi][ni][1] + b1};
                float2 v1 = {acc[mi][ni][2] + b0, acc[mi][ni][3] + b1};
                *(float2*)(Cf + (size_t)r0 * KDIM + col) = v0;
                *(float2*)(Cf + (size_t)(r0 + 8) * KDIM + col) = v1;
            } else {
                uint32_t h0, l0, h1, l1;
                pack_hl(acc[mi][ni][0], acc[mi][ni][1], h0, l0);
                pack_hl(acc[mi][ni][2], acc[mi][ni][3], h1, l1);
                *(uint32_t*)(Chi + (size_t)r0 * KDIM + col) = h0;
                *(uint32_t*)(Clo + (size_t)r0 * KDIM + col) = l0;
                *(uint32_t*)(Chi + (size_t)(r0 + 8) * KDIM + col) = h1;
                *(uint32_t*)(Clo + (size_t)(r0 + 8) * KDIM + col) = l1;
            }
        }
    }
}

// ---------------------------------------------------------------------------
// Tensor-core flash attention (bf16x3). CTA = (128 queries, one b,h).
// 8 warps x 16 query rows. K/V tiles of 64 keys, double-buffered cp.async.
// QK^T: Q A-frags preloaded; K via ldmatrix. P reuses C-frag layout as A-frag.
// PV: V via ldmatrix.trans from [key][dim] layout.
// ---------------------------------------------------------------------------
#define ROWQ    144                  // smem row bytes: 64 bf16 + pad
#define QH_OFF  0
#define QL_OFF  18432                // 128*144
#define ST_OFF  36864
#define ST_SZ   36864                // KH|KL|VH|VL each 64*144=9216
#define SMEM_ATT 110592

__global__ __launch_bounds__(256) void attn_mma()
{
    extern __shared__ char smem_raw[];
    const uint32_t base = smem_u32(smem_raw);

    const int tid  = threadIdx.x;
    const int warp = tid >> 5;
    const int lane = tid & 31;
    const int qt = blockIdx.x;       // 0..15
    const int bh = blockIdx.y;       // 0..63
    const int b = bh >> 4;
    const int h = bh & 15;

    const size_t qrow0 = ((size_t)(b * TLEN + qt * 128)) * KDIM + h * HS;

    // ---- Q load (hi+lo), one group ----
#pragma unroll
    for (int it = 0; it < 8; it++) {
        int idx = it * 256 + tid;            // 0..2047
        int which = idx >> 10;               // 0=hi 1=lo
        int rem = idx & 1023;
        int r = rem >> 3;
        int ch = (rem & 7) << 4;
        const __nv_bfloat16* src = (which ? g_ql : g_qh) + qrow0 + (size_t)r * KDIM;
        cp16(base + (uint32_t)(which * QL_OFF + r * ROWQ + ch), (const char*)src + ch);
    }
    asm volatile("cp.async.commit_group;" ::: "memory");

    auto load_kv = [&](int c) {
        const __nv_bfloat16* arrs[4] = {g_kh, g_kl, g_vh, g_vl};
        uint32_t st = base + ST_OFF + (uint32_t)(c & 1) * ST_SZ;
        size_t krow0 = ((size_t)(b * TLEN + c * 64)) * KDIM + h * HS;
#pragma unroll
        for (int it = 0; it < 8; it++) {
            int idx = it * 256 + tid;        // 0..2047
            int which = idx >> 9;            // 0..3
            int rem = idx & 511;
            int r = rem >> 3;
            int ch = (rem & 7) << 4;
            const __nv_bfloat16* src = arrs[which] + krow0 + (size_t)r * KDIM;
            cp16(st + (uint32_t)(which * 9216 + r * ROWQ + ch), (const char*)src + ch);
        }
        asm volatile("cp.async.commit_group;" ::: "memory");
    };

    load_kv(0);
    load_kv(1);

    asm volatile("cp.async.wait_group 2;" ::: "memory");   // Q ready
    __syncthreads();

    // ---- preload Q fragments (per warp, 16 rows x 64 dims, hi+lo) ----
    uint32_t qfh[4][4], qfl[4][4];
    {
        uint32_t qb = base + (uint32_t)((warp * 16 + (lane & 15)) * ROWQ);
#pragma unroll
        for (int ks = 0; ks < 4; ks++) {
            uint32_t colb = (uint32_t)(ks * 32 + (lane >> 4) * 16);
            ldm_x4(qfh[ks], qb + colb);
            ldm_x4(qfl[ks], qb + QL_OFF + colb);
        }
    }

    const float scale = 0.03125f;    // 1/sqrt(1024)
    float m0 = -1e30f, m1 = -1e30f, l0 = 0.f, l1 = 0.f;
    float O[8][4];
#pragma unroll
    for (int t = 0; t < 8; t++)
#pragma unroll
        for (int e = 0; e < 4; e++) O[t][e] = 0.f;

    for (int c = 0; c < 32; c++) {
        if (c == 31) asm volatile("cp.async.wait_group 0;" ::: "memory");
        else         asm volatile("cp.async.wait_group 1;" ::: "memory");
        __syncthreads();

        uint32_t st = base + ST_OFF + (uint32_t)(c & 1) * ST_SZ;

        // ---- S = Q K^T ----
        float S[8][4];
#pragma unroll
        for (int t = 0; t < 8; t++)
#pragma unroll
            for (int e = 0; e < 4; e++) S[t][e] = 0.f;

#pragma unroll
        for (int ks = 0; ks < 4; ks++) {
            uint32_t kh4[4][4], kl4[4][4];
            uint32_t colb = (uint32_t)(ks * 32 + (lane >> 4) * 16);
#pragma unroll
            for (int ng = 0; ng < 4; ng++) {
                uint32_t ad = st + (uint32_t)((ng * 16 + (lane & 15)) * ROWQ) + colb;
                ldm_x4(kh4[ng], ad);
                ldm_x4(kl4[ng], ad + 9216);
            }
#pragma unroll
            for (int ng = 0; ng < 4; ng++)
#pragma unroll
                for (int s = 0; s < 2; s++) {
                    int nt = ng * 2 + s;
                    mma16816(S[nt], qfh[ks], kh4[ng][s], kh4[ng][s + 2]);
                    mma16816(S[nt], qfh[ks], kl4[ng][s], kl4[ng][s + 2]);
                    mma16816(S[nt], qfl[ks], kh4[ng][s], kh4[ng][s + 2]);
                }
        }

        // ---- online softmax (rows r = lane>>2 and r+8) ----
        float mx0 = -1e30f, mx1 = -1e30f;
#pragma unroll
        for (int t = 0; t < 8; t++) {
            S[t][0] *= scale; S[t][1] *= scale; S[t][2] *= scale; S[t][3] *= scale;
            mx0 = fmaxf(mx0, fmaxf(S[t][0], S[t][1]));
            mx1 = fmaxf(mx1, fmaxf(S[t][2], S[t][3]));
        }
        mx0 = fmaxf(mx0, __shfl_xor_sync(0xffffffffu, mx0, 1));
        mx0 = fmaxf(mx0, __shfl_xor_sync(0xffffffffu, mx0, 2));
        mx1 = fmaxf(mx1, __shfl_xor_sync(0xffffffffu, mx1, 1));
        mx1 = fmaxf(mx1, __shfl_xor_sync(0xffffffffu, mx1, 2));
        float mn0 = fmaxf(m0, mx0), mn1 = fmaxf(m1, mx1);
        float a0 = __expf(m0 - mn0), a1 = __expf(m1 - mn1);
        m0 = mn0; m1 = mn1;
        float sum0 = 0.f, sum1 = 0.f;
#pragma unroll
        for (int t = 0; t < 8; t++) {
            S[t][0] = __expf(S[t][0] - m0);
            S[t][1] = __expf(S[t][1] - m0);
            S[t][2] = __expf(S[t][2] - m1);
            S[t][3] = __expf(S[t][3] - m1);
            sum0 += S[t][0] + S[t][1];
            sum1 += S[t][2] + S[t][3];
        }
        sum0 += __shfl_xor_sync(0xffffffffu, sum0, 1);
        sum0 += __shfl_xor_sync(0xffffffffu, sum0, 2);
        sum1 += __shfl_xor_sync(0xffffffffu, sum1, 1);
        sum1 += __shfl_xor_sync(0xffffffffu, sum1, 2);
        l0 = l0 * a0 + sum0;
        l1 = l1 * a1 + sum1;
#pragma unroll
        for (int t = 0; t < 8; t++) {
            O[t][0] *= a0; O[t][1] *= a0; O[t][2] *= a1; O[t][3] *= a1;
        }

        // ---- P -> A fragments (C-frag layout == A-frag layout) ----
        uint32_t pah[4][4], pal[4][4];
#pragma unroll
        for (int j = 0; j < 4; j++) {
            pack_hl(S[2 * j][0],     S[2 * j][1],     pah[j][0], pal[j][0]);
            pack_hl(S[2 * j][2],     S[2 * j][3],     pah[j][1], pal[j][1]);
            pack_hl(S[2 * j + 1][0], S[2 * j + 1][1], pah[j][2], pal[j][2]);
            pack_hl(S[2 * j + 1][2], S[2 * j + 1][3], pah[j][3], pal[j][3]);
        }

        // ---- O += P V  (V via ldmatrix.trans) ----
#pragma unroll
        for (int ks = 0; ks < 4; ks++) {
            uint32_t vh4[4][4], vl4[4][4];
            uint32_t krow = (uint32_t)(ks * 16 + (lane & 7) + ((lane & 16) >> 1));
            uint32_t nb = (uint32_t)(((lane >> 3) & 1) * 16);
#pragma unroll
            for (int dg = 0; dg < 4; dg++) {
                uint32_t ad = st + 18432 + krow * ROWQ + (uint32_t)(dg * 32) + nb;
                ldm_x4t(vh4[dg], ad);
                ldm_x4t(vl4[dg], ad + 9216);
            }
#pragma unroll
            for (int dg = 0; dg < 4; dg++)
#pragma unroll
                for (int s = 0; s < 2; s++) {
                    int nt = dg * 2 + s;
                    mma16816(O[nt], pah[ks], vh4[dg][s], vh4[dg][s + 2]);
                    mma16816(O[nt], pah[ks], vl4[dg][s], vl4[dg][s + 2]);
                    mma16816(O[nt], pal[ks], vh4[dg][s], vh4[dg][s + 2]);
                }
        }

        __syncthreads();
        if (c + 2 < 32) load_kv(c + 2);
    }

    // ---- epilogue: normalize, split hi/lo, store ----
    float inv0 = 1.f / l0, inv1 = 1.f / l1;
    size_t orow0 = ((size_t)(b * TLEN + qt * 128 + warp * 16 + (lane >> 2))) * KDIM + h * HS;
    size_t orow1 = orow0 + (size_t)8 * KDIM;
#pragma unroll
    for (int t = 0; t < 8; t++) {
        int col = t * 8 + 2 * (lane & 3);
        uint32_t h0, l0u, h1, l1u;
        pack_hl(O[t][0] * inv0, O[t][1] * inv0, h0, l0u);
        pack_hl(O[t][2] * inv1, O[t][3] * inv1, h1, l1u);
        *(uint32_t*)(g_ahi + orow0 + col) = h0;
        *(uint32_t*)(g_alo + orow0 + col) = l0u;
        *(uint32_t*)(g_ahi + orow1 + col) = h1;
        *(uint32_t*)(g_alo + orow1 + col) = l1u;
    }
}

// ---------------------------------------------------------------------------
extern "C" void kernel_launch(void* const* d_in, const int* in_sizes, int n_in,
                              void* d_out, int out_size)
{
    const float* x  = (const float*)d_in[0];
    const float* Wk = (const float*)d_in[1];
    const float* Wq = (const float*)d_in[2];
    const float* Wv = (const float*)d_in[3];
    const float* Wu = (const float*)d_in[4];
    const float* bu = (const float*)d_in[5];
    float* out = (float*)d_out;

    cudaFuncSetAttribute(gemm_mma, cudaFuncAttributeMaxDynamicSharedMemorySize, SMEM_REQ);
    cudaFuncSetAttribute(attn_mma, cudaFuncAttributeMaxDynamicSharedMemorySize, SMEM_ATT);

    __nv_bfloat16 *ahi, *alo, *whi, *wlo, *qh, *ql, *kh, *kl, *vh, *vl;
    cudaGetSymbolAddress((void**)&ahi, g_ahi);
    cudaGetSymbolAddress((void**)&alo, g_alo);
    cudaGetSymbolAddress((void**)&whi, g_whi);
    cudaGetSymbolAddress((void**)&wlo, g_wlo);
    cudaGetSymbolAddress((void**)&qh, g_qh);
    cudaGetSymbolAddress((void**)&ql, g_ql);
    cudaGetSymbolAddress((void**)&kh, g_kh);
    cudaGetSymbolAddress((void**)&kl, g_kl);
    cudaGetSymbolAddress((void**)&vh, g_vh);
    cudaGetSymbolAddress((void**)&vl, g_vl);

    const int nx4 = MROWS * KDIM / 4;
    const int nw4 = KDIM * KDIM / 4;
    const size_t WSZ = (size_t)KDIM * KDIM;

    split_bf16<<<nx4 / 256, 256>>>(x, ahi, alo, nx4);
    split_bf16<<<nw4 / 256, 256>>>(Wq, whi + 0 * WSZ, wlo + 0 * WSZ, nw4);
    split_bf16<<<nw4 / 256, 256>>>(Wk, whi + 1 * WSZ, wlo + 1 * WSZ, nw4);
    split_bf16<<<nw4 / 256, 256>>>(Wv, whi + 2 * WSZ, wlo + 2 * WSZ, nw4);
    split_bf16<<<nw4 / 256, 256>>>(Wu, whi + 3 * WSZ, wlo + 3 * WSZ, nw4);

    dim3 gg(KDIM / 128, MROWS / 128);   // (8, 64)
    gemm_mma<<<gg, 256, SMEM_REQ>>>(ahi, alo, whi + 0 * WSZ, wlo + 0 * WSZ,
                                    nullptr, nullptr, qh, ql);
    gemm_mma<<<gg, 256, SMEM_REQ>>>(ahi, alo, whi + 1 * WSZ, wlo + 1 * WSZ,
                                    nullptr, nullptr, kh, kl);
    gemm_mma<<<gg, 256, SMEM_REQ>>>(ahi, alo, whi + 2 * WSZ, wlo + 2 * WSZ,
                                    nullptr, nullptr, vh, vl);

    attn_mma<<<dim3(16, 64), 256, SMEM_ATT>>>();

    gemm_mma<<<gg, 256, SMEM_REQ>>>(ahi, alo, whi + 3 * WSZ, wlo + 3 * WSZ,
                                    out, bu, nullptr, nullptr);
}